// round 15
// baseline (speedup 1.0000x reference)
#include <cuda_runtime.h>
#include <math.h>

#define D 8192
#define M_TIME 16
#define KWTA_K (D / 8)
#define ROWS 8
#define GTHREADS 256
#define ROW_BYTES (D * 4)              // 32 KB per row
#define ROW_F4 (D / 4)                 // 2048 float4 per row
#define SLOTS 8                        // float4 slots per thread per row
#define SMEM_BYTES (2 * ROW_BYTES)     // 64 KB double buffer
#define NPART 8                        // sumsq partial blocks: 8*256*4 = D

// Scratch (device globals — no allocation allowed)
__device__ __align__(16) float g_x[D]; // (x_in+pred)*g_norm, UNSCALED by rms
__device__ float g_partials[NPART];
__device__ __align__(16) float g_rpre[D];
__device__ __align__(16) float g_k[D];
__device__ __align__(16) float g_v[D];
__device__ __align__(16) float g_y[D];
__device__ __align__(16) float g_h[D];

__device__ __forceinline__ float softplusf(float x) {
    if (x > 20.f) return x;
    if (x < -20.f) return expf(x);
    return log1pf(expf(x));
}

// ---- TMA bulk + mbarrier primitives --------------------------------------
__device__ __forceinline__ unsigned smem_u32(const void* p) {
    return (unsigned)__cvta_generic_to_shared(p);
}
__device__ __forceinline__ void mbar_init(unsigned mbar, unsigned count) {
    asm volatile("mbarrier.init.shared.b64 [%0], %1;" :: "r"(mbar), "r"(count) : "memory");
}
__device__ __forceinline__ void mbar_expect_tx(unsigned mbar, unsigned bytes) {
    asm volatile("mbarrier.arrive.expect_tx.shared.b64 _, [%0], %1;"
                 :: "r"(mbar), "r"(bytes) : "memory");
}
__device__ __forceinline__ void mbar_wait(unsigned mbar, unsigned parity) {
    asm volatile(
        "{\n\t"
        ".reg .pred P1;\n\t"
        "LAB_WAIT_%=:\n\t"
        "mbarrier.try_wait.parity.acquire.cta.shared::cta.b64 P1, [%0], %1;\n\t"
        "@P1 bra LAB_DONE_%=;\n\t"
        "bra LAB_WAIT_%=;\n\t"
        "LAB_DONE_%=:\n\t"
        "}"
        :: "r"(mbar), "r"(parity) : "memory");
}
__device__ __forceinline__ void tma_bulk_g2s(unsigned dst_smem, const void* gsrc,
                                             unsigned bytes, unsigned mbar) {
    asm volatile(
        "cp.async.bulk.shared::cluster.global.mbarrier::complete_tx::bytes "
        "[%0], [%1], %2, [%3];"
        :: "r"(dst_smem), "l"(gsrc), "r"(bytes), "r"(mbar) : "memory");
}
// L2 bulk prefetch (data is consumed later by TMA -> turns cold DRAM hits
// at kernel start into L2 hits; zero wasted traffic).
__device__ __forceinline__ void l2_prefetch(const void* gsrc, unsigned bytes) {
    asm volatile("cp.async.bulk.prefetch.L2.global [%0], %1;"
                 :: "l"(gsrc), "r"(bytes) : "memory");
}

// ---------------------------------------------------------------------------
// K0: prep — xg = (x_in+pred)*g_norm, deterministic sumsq partials,
// plus L2 prefetch of the head of Wr (gemv3's first-wave working set).
// 8 blocks x 256 threads.
// ---------------------------------------------------------------------------
__global__ void prep_kernel(const float* __restrict__ x_in,
                            const float* __restrict__ pred,
                            const float* __restrict__ g_norm,
                            const float* __restrict__ Wr) {
    int i4 = blockIdx.x * 256 + threadIdx.x;   // float4 index in [0, D/4)
    const float4* xi = (const float4*)x_in;
    const float4* pi = (const float4*)pred;
    const float4* gi = (const float4*)g_norm;
    float4 x4 = xi[i4], p4 = pi[i4], g4 = gi[i4];
    float4 t4 = make_float4(x4.x + p4.x, x4.y + p4.y, x4.z + p4.z, x4.w + p4.w);
    ((float4*)g_x)[i4] = make_float4(t4.x * g4.x, t4.y * g4.y, t4.z * g4.z, t4.w * g4.w);
    float s = t4.x * t4.x + t4.y * t4.y + t4.z * t4.z + t4.w * t4.w;
#pragma unroll
    for (int o = 16; o > 0; o >>= 1) s += __shfl_xor_sync(0xFFFFFFFFu, s, o);
    __shared__ float sw[8];
    if ((threadIdx.x & 31) == 0) sw[threadIdx.x >> 5] = s;
    __syncthreads();
    if (threadIdx.x == 0) {
        g_partials[blockIdx.x] = sw[0] + sw[1] + sw[2] + sw[3]
                               + sw[4] + sw[5] + sw[6] + sw[7];
    }
    // Prefetch first 32 MB of Wr into L2 (covers gemv3 first-wave stages).
    // 2048 threads x 16 KB each.
    {
        int tid = blockIdx.x * 256 + threadIdx.x;       // 0..2047
        const char* src = (const char*)Wr + (size_t)tid * 16384;
        l2_prefetch(src, 16384);
    }
}

__device__ __forceinline__ float rms_scale() {
    float ss = 0.f;
#pragma unroll
    for (int i = 0; i < NPART; i++) ss += g_partials[i];
    return rsqrtf(ss / (float)D + 1e-6f);
}

// ---------------------------------------------------------------------------
// TMA-fed GEMV: one CTA computes ROWS=8 consecutive rows of W @ vec.
// Stage = one full 32 KB row, fetched by ONE cp.async.bulk (TMA engine),
// double-buffered with two mbarriers. Thread t consumes float4 slots
// (t + 256j), j=0..7 from the staged row.
// mode: 0 = dst[row] = scale * dot           (gemv3)
//       1 = dst[row] = scale*g_x[row] + dot  (gemv_o)
// ---------------------------------------------------------------------------
__device__ __forceinline__ void gemv_pipe_tma(const float* __restrict__ W,
                                              const float* __restrict__ vec,
                                              int rowbase,
                                              float* __restrict__ dst,
                                              int mode) {
    extern __shared__ __align__(128) float4 sbuf[];   // [2][ROW_F4]
    __shared__ __align__(8) unsigned long long mbar_store[2];
    __shared__ float sred[GTHREADS / 32][ROWS];
    __shared__ float s_scale;

    const int t = threadIdx.x;
    const unsigned mb0 = smem_u32(&mbar_store[0]);
    const unsigned mb1 = smem_u32(&mbar_store[1]);

    if (t == 0) {
        mbar_init(mb0, 1);
        mbar_init(mb1, 1);
        asm volatile("fence.proxy.async.shared::cta;" ::: "memory");
    }
    __syncthreads();

    if (t == 0) {
        mbar_expect_tx(mb0, ROW_BYTES);
        tma_bulk_g2s(smem_u32(sbuf), W + (size_t)rowbase * D, ROW_BYTES, mb0);
        mbar_expect_tx(mb1, ROW_BYTES);
        tma_bulk_g2s(smem_u32(sbuf + ROW_F4), W + (size_t)(rowbase + 1) * D,
                     ROW_BYTES, mb1);
    }

    // Register-cache this thread's slice of the input vector.
    const float4* xv = (const float4*)vec;
    float4 xr[SLOTS];
#pragma unroll
    for (int j = 0; j < SLOTS; j++) xr[j] = xv[t + 256 * j];

    float acc[ROWS];
#pragma unroll
    for (int r = 0; r < ROWS; r++) {
        const unsigned mb = (r & 1) ? mb1 : mb0;
        mbar_wait(mb, (r >> 1) & 1);

        const float4* sb = sbuf + (r & 1) * ROW_F4 + t;
        float a0 = 0.f, a1 = 0.f;
#pragma unroll
        for (int j = 0; j < SLOTS; j += 2) {
            float4 w0 = sb[256 * j],       x0 = xr[j];
            float4 w1 = sb[256 * (j + 1)], x1 = xr[j + 1];
            a0 += w0.x * x0.x + w0.y * x0.y + w0.z * x0.z + w0.w * x0.w;
            a1 += w1.x * x1.x + w1.y * x1.y + w1.z * x1.z + w1.w * x1.w;
        }
        acc[r] = a0 + a1;

        __syncthreads();   // whole CTA done reading stage (r&1)
        if (r + 2 < ROWS && t == 0) {
            mbar_expect_tx(mb, ROW_BYTES);
            tma_bulk_g2s(smem_u32(sbuf + (r & 1) * ROW_F4),
                         W + (size_t)(rowbase + r + 2) * D, ROW_BYTES, mb);
        }
    }

#pragma unroll
    for (int r = 0; r < ROWS; r++) {
#pragma unroll
        for (int o = 16; o > 0; o >>= 1)
            acc[r] += __shfl_xor_sync(0xFFFFFFFFu, acc[r], o);
    }

    int warp = t >> 5;
    int lane = t & 31;
    if (lane == 0) {
#pragma unroll
        for (int r = 0; r < ROWS; r++) sred[warp][r] = acc[r];
    }
    if (t == 0) s_scale = rms_scale();
    __syncthreads();
    if (t < ROWS) {
        float s = 0.f;
#pragma unroll
        for (int w = 0; w < GTHREADS / 32; w++) s += sred[w][t];
        int row = rowbase + t;
        if (mode == 0) dst[row] = s_scale * s;
        else           dst[row] = s_scale * g_x[row] + s;
    }
}

// K1: fused Wr/Wk/Wv GEMV (scale folded into epilogue). grid = 3072
__global__ void __launch_bounds__(GTHREADS, 3)
gemv3_kernel(const float* __restrict__ Wr,
             const float* __restrict__ Wk,
             const float* __restrict__ Wv) {
    const int blocks_per_mat = D / ROWS;  // 1024
    int mat = blockIdx.x / blocks_per_mat;
    int rowbase = (blockIdx.x % blocks_per_mat) * ROWS;
    const float* W = (mat == 0) ? Wr : ((mat == 1) ? Wk : Wv);
    float* dst = (mat == 0) ? g_rpre : ((mat == 1) ? g_k : g_v);
    gemv_pipe_tma(W, g_x, rowbase, dst, 0);
}

// K3: h = scale*xg + Wo @ y. grid = 1024
__global__ void __launch_bounds__(GTHREADS, 3)
gemv_o_kernel(const float* __restrict__ Wo) {
    int rowbase = blockIdx.x * ROWS;
    gemv_pipe_tma(Wo, g_y, rowbase, g_h, 1);
}

// ---------------------------------------------------------------------------
// K2: elementwise (decay, RoPE, Kalman gate) -> y, plus L2 prefetch of the
// head of Wo (gemv_o's first-wave working set). 32 blocks x 256 threads.
// ---------------------------------------------------------------------------
__global__ void elemwise_kernel(const float* __restrict__ step_pos,
                                const float* __restrict__ state_num,
                                const float* __restrict__ state_den,
                                const float* __restrict__ state_var,
                                const float* __restrict__ raw_decay,
                                const float* __restrict__ pn_param,
                                const float* __restrict__ on_param,
                                const float* __restrict__ W_time,
                                const float* __restrict__ Wo) {
    int i = blockIdx.x * 256 + threadIdx.x;
    if (i >= D) return;

    // Prefetch first 32 MB of Wo into L2 (8192 threads x 4 KB).
    l2_prefetch((const char*)Wo + (size_t)i * 4096, 4096);

    float k = g_k[i];
    float v = g_v[i];
    if (i < 2 * M_TIME) {
        int m = i >> 1;
        float th = step_pos[0] * W_time[m];
        float c, s;
        sincosf(th, &s, &c);
        float v0 = g_v[2 * m];
        float v1 = g_v[2 * m + 1];
        v = (i & 1) ? (v0 * s + v1 * c) : (v0 * c - v1 * s);
    }

    float sp = softplusf(raw_decay[i]);
    float rate = fmaxf(-sp, -30.f);
    float lam = fmaxf(expf(rate), 1e-6f);
    float pn = fminf(fmaxf(softplusf(pn_param[0]), 1e-6f), 1e4f);
    float on = fminf(fmaxf(softplusf(on_param[0]), 1e-6f), 1e4f);

    float sn = state_num[i] * lam;
    float sd = state_den[i] * lam;
    float sv = state_var[i] * lam * lam + pn;

    float r = 1.f / (1.f + expf(-g_rpre[i]));
    float w = expf(fminf(k, 30.f));
    float pred_state = sn / (sd + 1e-6f);
    float msg = w * v;
    float resid = msg - pred_state;
    float obs_var = expf(fminf(-k, 30.f)) * on + 1e-6f;
    float gain = sv / (sv + obs_var);
    gain = fminf(fmaxf(gain, 1e-6f), 1.f - 1e-6f);
    float new_state = pred_state + gain * resid;
    g_y[i] = r * new_state;
}

// ---------------------------------------------------------------------------
// K4: exact KWTA_K-th-largest (radix select) + threshold. (proven gmem ver.)
// ---------------------------------------------------------------------------
__global__ void topk_kernel(float* __restrict__ out) {
    __shared__ unsigned hist[256];
    __shared__ unsigned s_prefix;
    __shared__ int s_K;
    __shared__ float s_thresh;

    if (threadIdx.x == 0) { s_prefix = 0u; s_K = KWTA_K; }
    __syncthreads();

    for (int pass = 3; pass >= 0; pass--) {
        if (threadIdx.x < 256) hist[threadIdx.x] = 0u;
        __syncthreads();
        unsigned prefmask = (pass == 3) ? 0u : (0xFFFFFFFFu << ((pass + 1) * 8));
        unsigned pref = s_prefix;
        for (int i = threadIdx.x; i < D; i += 1024) {
            unsigned u = __float_as_uint(g_h[i]);
            unsigned key = (u & 0x80000000u) ? ~u : (u | 0x80000000u);
            if ((key & prefmask) == (pref & prefmask)) {
                atomicAdd(&hist[(key >> (pass * 8)) & 255u], 1u);
            }
        }
        __syncthreads();
        if (threadIdx.x == 0) {
            int K = s_K;
            unsigned cum = 0;
            int b = 255;
            for (; b >= 0; b--) {
                cum += hist[b];
                if ((int)cum >= K) break;
            }
            s_K = K - (int)(cum - hist[b]);
            s_prefix = s_prefix | ((unsigned)b << (pass * 8));
        }
        __syncthreads();
    }

    if (threadIdx.x == 0) {
        unsigned key = s_prefix;
        unsigned u = (key & 0x80000000u) ? (key ^ 0x80000000u) : ~key;
        s_thresh = __uint_as_float(u);
    }
    __syncthreads();

    float th = s_thresh;
    for (int i = threadIdx.x; i < D; i += 1024) {
        float h = g_h[i];
        out[i] = (h >= th) ? h : 0.f;
    }
}

// ---------------------------------------------------------------------------
// Launch
// ---------------------------------------------------------------------------
extern "C" void kernel_launch(void* const* d_in, const int* in_sizes, int n_in,
                              void* d_out, int out_size) {
    const float* x_in      = (const float*)d_in[0];
    const float* step_pos  = (const float*)d_in[1];
    const float* pred      = (const float*)d_in[2];
    const float* state_num = (const float*)d_in[3];
    const float* state_den = (const float*)d_in[4];
    const float* state_var = (const float*)d_in[5];
    const float* Wr        = (const float*)d_in[6];
    const float* Wk        = (const float*)d_in[7];
    const float* Wv        = (const float*)d_in[8];
    const float* Wo        = (const float*)d_in[9];
    const float* raw_decay = (const float*)d_in[10];
    const float* pn_param  = (const float*)d_in[11];
    const float* on_param  = (const float*)d_in[12];
    const float* g_norm    = (const float*)d_in[13];
    const float* W_time    = (const float*)d_in[14];
    float* out = (float*)d_out;

    cudaFuncSetAttribute(gemv3_kernel,
                         cudaFuncAttributeMaxDynamicSharedMemorySize, SMEM_BYTES);
    cudaFuncSetAttribute(gemv_o_kernel,
                         cudaFuncAttributeMaxDynamicSharedMemorySize, SMEM_BYTES);

    prep_kernel<<<NPART, 256>>>(x_in, pred, g_norm, Wr);
    gemv3_kernel<<<3 * (D / ROWS), GTHREADS, SMEM_BYTES>>>(Wr, Wk, Wv);
    elemwise_kernel<<<D / 256, 256>>>(step_pos, state_num, state_den, state_var,
                                      raw_decay, pn_param, on_param, W_time, Wo);
    gemv_o_kernel<<<D / ROWS, GTHREADS, SMEM_BYTES>>>(Wo);
    topk_kernel<<<1, 1024>>>(out);
}

// round 16
// speedup vs baseline: 1.0801x; 1.0801x over previous
#include <cuda_runtime.h>
#include <math.h>

#define D 8192
#define M_TIME 16
#define KWTA_K (D / 8)
#define ROWS 8
#define GTHREADS 256
#define ROW_BYTES (D * 4)              // 32 KB per row
#define ROW_F4 (D / 4)                 // 2048 float4 per row
#define SLOTS 8                        // float4 slots per thread per row
#define SMEM_BYTES (2 * ROW_BYTES)     // 64 KB double buffer
#define NPART 8                        // sumsq partial blocks: 8*256*4 = D

// Scratch (device globals — no allocation allowed)
__device__ __align__(16) float g_x[D]; // (x_in+pred)*g_norm, UNSCALED by rms
__device__ float g_partials[NPART];
__device__ __align__(16) float g_rpre[D];
__device__ __align__(16) float g_k[D];
__device__ __align__(16) float g_v[D];
__device__ __align__(16) float g_y[D];
__device__ __align__(16) float g_h[D];

__device__ __forceinline__ float softplusf(float x) {
    if (x > 20.f) return x;
    if (x < -20.f) return expf(x);
    return log1pf(expf(x));
}

// ---- TMA bulk + mbarrier primitives --------------------------------------
__device__ __forceinline__ unsigned smem_u32(const void* p) {
    return (unsigned)__cvta_generic_to_shared(p);
}
__device__ __forceinline__ void mbar_init(unsigned mbar, unsigned count) {
    asm volatile("mbarrier.init.shared.b64 [%0], %1;" :: "r"(mbar), "r"(count) : "memory");
}
__device__ __forceinline__ void mbar_expect_tx(unsigned mbar, unsigned bytes) {
    asm volatile("mbarrier.arrive.expect_tx.shared.b64 _, [%0], %1;"
                 :: "r"(mbar), "r"(bytes) : "memory");
}
__device__ __forceinline__ void mbar_wait(unsigned mbar, unsigned parity) {
    asm volatile(
        "{\n\t"
        ".reg .pred P1;\n\t"
        "LAB_WAIT_%=:\n\t"
        "mbarrier.try_wait.parity.acquire.cta.shared::cta.b64 P1, [%0], %1;\n\t"
        "@P1 bra LAB_DONE_%=;\n\t"
        "bra LAB_WAIT_%=;\n\t"
        "LAB_DONE_%=:\n\t"
        "}"
        :: "r"(mbar), "r"(parity) : "memory");
}
__device__ __forceinline__ void tma_bulk_g2s(unsigned dst_smem, const void* gsrc,
                                             unsigned bytes, unsigned mbar) {
    asm volatile(
        "cp.async.bulk.shared::cluster.global.mbarrier::complete_tx::bytes "
        "[%0], [%1], %2, [%3];"
        :: "r"(dst_smem), "l"(gsrc), "r"(bytes), "r"(mbar) : "memory");
}

// ---------------------------------------------------------------------------
// K0: prep — xg = (x_in+pred)*g_norm, and deterministic sumsq partials.
// 8 blocks x 256 threads; each thread handles exactly one float4 (8*256*4=D).
// ---------------------------------------------------------------------------
__global__ void prep_kernel(const float* __restrict__ x_in,
                            const float* __restrict__ pred,
                            const float* __restrict__ g_norm) {
    int i4 = blockIdx.x * 256 + threadIdx.x;   // float4 index in [0, D/4)
    const float4* xi = (const float4*)x_in;
    const float4* pi = (const float4*)pred;
    const float4* gi = (const float4*)g_norm;
    float4 x4 = xi[i4], p4 = pi[i4], g4 = gi[i4];
    float4 t4 = make_float4(x4.x + p4.x, x4.y + p4.y, x4.z + p4.z, x4.w + p4.w);
    ((float4*)g_x)[i4] = make_float4(t4.x * g4.x, t4.y * g4.y, t4.z * g4.z, t4.w * g4.w);
    float s = t4.x * t4.x + t4.y * t4.y + t4.z * t4.z + t4.w * t4.w;
#pragma unroll
    for (int o = 16; o > 0; o >>= 1) s += __shfl_xor_sync(0xFFFFFFFFu, s, o);
    __shared__ float sw[8];
    if ((threadIdx.x & 31) == 0) sw[threadIdx.x >> 5] = s;
    __syncthreads();
    if (threadIdx.x == 0) {
        g_partials[blockIdx.x] = sw[0] + sw[1] + sw[2] + sw[3]
                               + sw[4] + sw[5] + sw[6] + sw[7];
    }
}

__device__ __forceinline__ float rms_scale() {
    float ss = 0.f;
#pragma unroll
    for (int i = 0; i < NPART; i++) ss += g_partials[i];
    return rsqrtf(ss / (float)D + 1e-6f);
}

// ---------------------------------------------------------------------------
// TMA-fed GEMV: one CTA computes ROWS=8 consecutive rows of W @ vec.
// Stage = one full 32 KB row, fetched by ONE cp.async.bulk (TMA engine),
// double-buffered with two mbarriers. Thread t consumes float4 slots
// (t + 256j), j=0..7 from the staged row.
// mode: 0 = dst[row] = scale * dot           (gemv3)
//       1 = dst[row] = scale*g_x[row] + dot  (gemv_o)
// ---------------------------------------------------------------------------
__device__ __forceinline__ void gemv_pipe_tma(const float* __restrict__ W,
                                              const float* __restrict__ vec,
                                              int rowbase,
                                              float* __restrict__ dst,
                                              int mode) {
    extern __shared__ __align__(128) float4 sbuf[];   // [2][ROW_F4]
    __shared__ __align__(8) unsigned long long mbar_store[2];
    __shared__ float sred[GTHREADS / 32][ROWS];
    __shared__ float s_scale;

    const int t = threadIdx.x;
    const unsigned mb0 = smem_u32(&mbar_store[0]);
    const unsigned mb1 = smem_u32(&mbar_store[1]);

    if (t == 0) {
        mbar_init(mb0, 1);
        mbar_init(mb1, 1);
        asm volatile("fence.proxy.async.shared::cta;" ::: "memory");
    }
    __syncthreads();

    if (t == 0) {
        mbar_expect_tx(mb0, ROW_BYTES);
        tma_bulk_g2s(smem_u32(sbuf), W + (size_t)rowbase * D, ROW_BYTES, mb0);
        mbar_expect_tx(mb1, ROW_BYTES);
        tma_bulk_g2s(smem_u32(sbuf + ROW_F4), W + (size_t)(rowbase + 1) * D,
                     ROW_BYTES, mb1);
    }

    // Register-cache this thread's slice of the input vector.
    const float4* xv = (const float4*)vec;
    float4 xr[SLOTS];
#pragma unroll
    for (int j = 0; j < SLOTS; j++) xr[j] = xv[t + 256 * j];

    float acc[ROWS];
#pragma unroll
    for (int r = 0; r < ROWS; r++) {
        const unsigned mb = (r & 1) ? mb1 : mb0;
        mbar_wait(mb, (r >> 1) & 1);

        const float4* sb = sbuf + (r & 1) * ROW_F4 + t;
        float a0 = 0.f, a1 = 0.f;
#pragma unroll
        for (int j = 0; j < SLOTS; j += 2) {
            float4 w0 = sb[256 * j],       x0 = xr[j];
            float4 w1 = sb[256 * (j + 1)], x1 = xr[j + 1];
            a0 += w0.x * x0.x + w0.y * x0.y + w0.z * x0.z + w0.w * x0.w;
            a1 += w1.x * x1.x + w1.y * x1.y + w1.z * x1.z + w1.w * x1.w;
        }
        acc[r] = a0 + a1;

        __syncthreads();   // whole CTA done reading stage (r&1)
        if (r + 2 < ROWS && t == 0) {
            mbar_expect_tx(mb, ROW_BYTES);
            tma_bulk_g2s(smem_u32(sbuf + (r & 1) * ROW_F4),
                         W + (size_t)(rowbase + r + 2) * D, ROW_BYTES, mb);
        }
    }

#pragma unroll
    for (int r = 0; r < ROWS; r++) {
#pragma unroll
        for (int o = 16; o > 0; o >>= 1)
            acc[r] += __shfl_xor_sync(0xFFFFFFFFu, acc[r], o);
    }

    int warp = t >> 5;
    int lane = t & 31;
    if (lane == 0) {
#pragma unroll
        for (int r = 0; r < ROWS; r++) sred[warp][r] = acc[r];
    }
    if (t == 0) s_scale = rms_scale();
    __syncthreads();
    if (t < ROWS) {
        float s = 0.f;
#pragma unroll
        for (int w = 0; w < GTHREADS / 32; w++) s += sred[w][t];
        int row = rowbase + t;
        if (mode == 0) dst[row] = s_scale * s;
        else           dst[row] = s_scale * g_x[row] + s;
    }
}

// K1: fused Wr/Wk/Wv GEMV (scale folded into epilogue). grid = 3072
__global__ void __launch_bounds__(GTHREADS, 3)
gemv3_kernel(const float* __restrict__ Wr,
             const float* __restrict__ Wk,
             const float* __restrict__ Wv) {
    const int blocks_per_mat = D / ROWS;  // 1024
    int mat = blockIdx.x / blocks_per_mat;
    int rowbase = (blockIdx.x % blocks_per_mat) * ROWS;
    const float* W = (mat == 0) ? Wr : ((mat == 1) ? Wk : Wv);
    float* dst = (mat == 0) ? g_rpre : ((mat == 1) ? g_k : g_v);
    gemv_pipe_tma(W, g_x, rowbase, dst, 0);
}

// K3: h = scale*xg + Wo @ y. grid = 1024
__global__ void __launch_bounds__(GTHREADS, 3)
gemv_o_kernel(const float* __restrict__ Wo) {
    int rowbase = blockIdx.x * ROWS;
    gemv_pipe_tma(Wo, g_y, rowbase, g_h, 1);
}

// ---------------------------------------------------------------------------
// K2: elementwise (decay, RoPE, Kalman gate) -> y   (proven)
// ---------------------------------------------------------------------------
__global__ void elemwise_kernel(const float* __restrict__ step_pos,
                                const float* __restrict__ state_num,
                                const float* __restrict__ state_den,
                                const float* __restrict__ state_var,
                                const float* __restrict__ raw_decay,
                                const float* __restrict__ pn_param,
                                const float* __restrict__ on_param,
                                const float* __restrict__ W_time) {
    int i = blockIdx.x * 256 + threadIdx.x;
    if (i >= D) return;

    float k = g_k[i];
    float v = g_v[i];
    if (i < 2 * M_TIME) {
        int m = i >> 1;
        float th = step_pos[0] * W_time[m];
        float c, s;
        sincosf(th, &s, &c);
        float v0 = g_v[2 * m];
        float v1 = g_v[2 * m + 1];
        v = (i & 1) ? (v0 * s + v1 * c) : (v0 * c - v1 * s);
    }

    float sp = softplusf(raw_decay[i]);
    float rate = fmaxf(-sp, -30.f);
    float lam = fmaxf(expf(rate), 1e-6f);
    float pn = fminf(fmaxf(softplusf(pn_param[0]), 1e-6f), 1e4f);
    float on = fminf(fmaxf(softplusf(on_param[0]), 1e-6f), 1e4f);

    float sn = state_num[i] * lam;
    float sd = state_den[i] * lam;
    float sv = state_var[i] * lam * lam + pn;

    float r = 1.f / (1.f + expf(-g_rpre[i]));
    float w = expf(fminf(k, 30.f));
    float pred_state = sn / (sd + 1e-6f);
    float msg = w * v;
    float resid = msg - pred_state;
    float obs_var = expf(fminf(-k, 30.f)) * on + 1e-6f;
    float gain = sv / (sv + obs_var);
    gain = fminf(fmaxf(gain, 1e-6f), 1.f - 1e-6f);
    float new_state = pred_state + gain * resid;
    g_y[i] = r * new_state;
}

// ---------------------------------------------------------------------------
// K4: exact KWTA_K-th-largest (radix select) + threshold. (proven gmem ver.)
// ---------------------------------------------------------------------------
__global__ void topk_kernel(float* __restrict__ out) {
    __shared__ unsigned hist[256];
    __shared__ unsigned s_prefix;
    __shared__ int s_K;
    __shared__ float s_thresh;

    if (threadIdx.x == 0) { s_prefix = 0u; s_K = KWTA_K; }
    __syncthreads();

    for (int pass = 3; pass >= 0; pass--) {
        if (threadIdx.x < 256) hist[threadIdx.x] = 0u;
        __syncthreads();
        unsigned prefmask = (pass == 3) ? 0u : (0xFFFFFFFFu << ((pass + 1) * 8));
        unsigned pref = s_prefix;
        for (int i = threadIdx.x; i < D; i += 1024) {
            unsigned u = __float_as_uint(g_h[i]);
            unsigned key = (u & 0x80000000u) ? ~u : (u | 0x80000000u);
            if ((key & prefmask) == (pref & prefmask)) {
                atomicAdd(&hist[(key >> (pass * 8)) & 255u], 1u);
            }
        }
        __syncthreads();
        if (threadIdx.x == 0) {
            int K = s_K;
            unsigned cum = 0;
            int b = 255;
            for (; b >= 0; b--) {
                cum += hist[b];
                if ((int)cum >= K) break;
            }
            s_K = K - (int)(cum - hist[b]);
            s_prefix = s_prefix | ((unsigned)b << (pass * 8));
        }
        __syncthreads();
    }

    if (threadIdx.x == 0) {
        unsigned key = s_prefix;
        unsigned u = (key & 0x80000000u) ? (key ^ 0x80000000u) : ~key;
        s_thresh = __uint_as_float(u);
    }
    __syncthreads();

    float th = s_thresh;
    for (int i = threadIdx.x; i < D; i += 1024) {
        float h = g_h[i];
        out[i] = (h >= th) ? h : 0.f;
    }
}

// ---------------------------------------------------------------------------
// Launch
// ---------------------------------------------------------------------------
extern "C" void kernel_launch(void* const* d_in, const int* in_sizes, int n_in,
                              void* d_out, int out_size) {
    const float* x_in      = (const float*)d_in[0];
    const float* step_pos  = (const float*)d_in[1];
    const float* pred      = (const float*)d_in[2];
    const float* state_num = (const float*)d_in[3];
    const float* state_den = (const float*)d_in[4];
    const float* state_var = (const float*)d_in[5];
    const float* Wr        = (const float*)d_in[6];
    const float* Wk        = (const float*)d_in[7];
    const float* Wv        = (const float*)d_in[8];
    const float* Wo        = (const float*)d_in[9];
    const float* raw_decay = (const float*)d_in[10];
    const float* pn_param  = (const float*)d_in[11];
    const float* on_param  = (const float*)d_in[12];
    const float* g_norm    = (const float*)d_in[13];
    const float* W_time    = (const float*)d_in[14];
    float* out = (float*)d_out;

    cudaFuncSetAttribute(gemv3_kernel,
                         cudaFuncAttributeMaxDynamicSharedMemorySize, SMEM_BYTES);
    cudaFuncSetAttribute(gemv_o_kernel,
                         cudaFuncAttributeMaxDynamicSharedMemorySize, SMEM_BYTES);

    prep_kernel<<<NPART, 256>>>(x_in, pred, g_norm);
    gemv3_kernel<<<3 * (D / ROWS), GTHREADS, SMEM_BYTES>>>(Wr, Wk, Wv);
    elemwise_kernel<<<D / 256, 256>>>(step_pos, state_num, state_den, state_var,
                                      raw_decay, pn_param, on_param, W_time);
    gemv_o_kernel<<<D / ROWS, GTHREADS, SMEM_BYTES>>>(Wo);
    topk_kernel<<<1, 1024>>>(out);
}

// round 17
// speedup vs baseline: 1.0825x; 1.0022x over previous
#include <cuda_runtime.h>
#include <math.h>

#define D 8192
#define M_TIME 16
#define KWTA_K (D / 8)
#define GTHREADS 256
#define ROW_BYTES (D * 4)              // 32 KB per row
#define ROW_F4 (D / 4)                 // 2048 float4 per row
#define SLOTS 8                        // float4 slots per thread per row
#define SMEM_BYTES (2 * ROW_BYTES)     // 64 KB double buffer
#define NPART 8                        // sumsq partial blocks: 8*256*4 = D

// Scratch (device globals — no allocation allowed)
__device__ __align__(16) float g_x[D]; // (x_in+pred)*g_norm, UNSCALED by rms
__device__ float g_partials[NPART];
__device__ __align__(16) float g_rpre[D];
__device__ __align__(16) float g_k[D];
__device__ __align__(16) float g_v[D];
__device__ __align__(16) float g_y[D];
__device__ __align__(16) float g_h[D];

__device__ __forceinline__ float softplusf(float x) {
    if (x > 20.f) return x;
    if (x < -20.f) return expf(x);
    return log1pf(expf(x));
}

// ---- TMA bulk + mbarrier primitives --------------------------------------
__device__ __forceinline__ unsigned smem_u32(const void* p) {
    return (unsigned)__cvta_generic_to_shared(p);
}
__device__ __forceinline__ void mbar_init(unsigned mbar, unsigned count) {
    asm volatile("mbarrier.init.shared.b64 [%0], %1;" :: "r"(mbar), "r"(count) : "memory");
}
__device__ __forceinline__ void mbar_expect_tx(unsigned mbar, unsigned bytes) {
    asm volatile("mbarrier.arrive.expect_tx.shared.b64 _, [%0], %1;"
                 :: "r"(mbar), "r"(bytes) : "memory");
}
__device__ __forceinline__ void mbar_wait(unsigned mbar, unsigned parity) {
    asm volatile(
        "{\n\t"
        ".reg .pred P1;\n\t"
        "LAB_WAIT_%=:\n\t"
        "mbarrier.try_wait.parity.acquire.cta.shared::cta.b64 P1, [%0], %1;\n\t"
        "@P1 bra LAB_DONE_%=;\n\t"
        "bra LAB_WAIT_%=;\n\t"
        "LAB_DONE_%=:\n\t"
        "}"
        :: "r"(mbar), "r"(parity) : "memory");
}
__device__ __forceinline__ void tma_bulk_g2s(unsigned dst_smem, const void* gsrc,
                                             unsigned bytes, unsigned mbar) {
    asm volatile(
        "cp.async.bulk.shared::cluster.global.mbarrier::complete_tx::bytes "
        "[%0], [%1], %2, [%3];"
        :: "r"(dst_smem), "l"(gsrc), "r"(bytes), "r"(mbar) : "memory");
}

// ---------------------------------------------------------------------------
// K0: prep — xg = (x_in+pred)*g_norm, and deterministic sumsq partials.
// 8 blocks x 256 threads; each thread handles exactly one float4 (8*256*4=D).
// ---------------------------------------------------------------------------
__global__ void prep_kernel(const float* __restrict__ x_in,
                            const float* __restrict__ pred,
                            const float* __restrict__ g_norm) {
    int i4 = blockIdx.x * 256 + threadIdx.x;   // float4 index in [0, D/4)
    const float4* xi = (const float4*)x_in;
    const float4* pi = (const float4*)pred;
    const float4* gi = (const float4*)g_norm;
    float4 x4 = xi[i4], p4 = pi[i4], g4 = gi[i4];
    float4 t4 = make_float4(x4.x + p4.x, x4.y + p4.y, x4.z + p4.z, x4.w + p4.w);
    ((float4*)g_x)[i4] = make_float4(t4.x * g4.x, t4.y * g4.y, t4.z * g4.z, t4.w * g4.w);
    float s = t4.x * t4.x + t4.y * t4.y + t4.z * t4.z + t4.w * t4.w;
#pragma unroll
    for (int o = 16; o > 0; o >>= 1) s += __shfl_xor_sync(0xFFFFFFFFu, s, o);
    __shared__ float sw[8];
    if ((threadIdx.x & 31) == 0) sw[threadIdx.x >> 5] = s;
    __syncthreads();
    if (threadIdx.x == 0) {
        g_partials[blockIdx.x] = sw[0] + sw[1] + sw[2] + sw[3]
                               + sw[4] + sw[5] + sw[6] + sw[7];
    }
}

__device__ __forceinline__ float rms_scale() {
    float ss = 0.f;
#pragma unroll
    for (int i = 0; i < NPART; i++) ss += g_partials[i];
    return rsqrtf(ss / (float)D + 1e-6f);
}

// ---------------------------------------------------------------------------
// TMA-fed GEMV: one CTA computes NR consecutive rows of W @ vec.
// Stage = one full 32 KB row, fetched by ONE cp.async.bulk (TMA engine),
// double-buffered with two mbarriers. Thread t consumes float4 slots
// (t + 256j), j=0..7 from the staged row.
// mode: 0 = dst[row] = scale * dot           (gemv3)
//       1 = dst[row] = scale*g_x[row] + dot  (gemv_o)
// ---------------------------------------------------------------------------
template <int NR>
__device__ __forceinline__ void gemv_pipe_tma(const float* __restrict__ W,
                                              const float* __restrict__ vec,
                                              int rowbase,
                                              float* __restrict__ dst,
                                              int mode) {
    extern __shared__ __align__(128) float4 sbuf[];   // [2][ROW_F4]
    __shared__ __align__(8) unsigned long long mbar_store[2];
    __shared__ float sred[GTHREADS / 32][NR];
    __shared__ float s_scale;

    const int t = threadIdx.x;
    const unsigned mb0 = smem_u32(&mbar_store[0]);
    const unsigned mb1 = smem_u32(&mbar_store[1]);

    if (t == 0) {
        mbar_init(mb0, 1);
        mbar_init(mb1, 1);
        asm volatile("fence.proxy.async.shared::cta;" ::: "memory");
    }
    __syncthreads();

    if (t == 0) {
        mbar_expect_tx(mb0, ROW_BYTES);
        tma_bulk_g2s(smem_u32(sbuf), W + (size_t)rowbase * D, ROW_BYTES, mb0);
        mbar_expect_tx(mb1, ROW_BYTES);
        tma_bulk_g2s(smem_u32(sbuf + ROW_F4), W + (size_t)(rowbase + 1) * D,
                     ROW_BYTES, mb1);
    }

    // Register-cache this thread's slice of the input vector.
    const float4* xv = (const float4*)vec;
    float4 xr[SLOTS];
#pragma unroll
    for (int j = 0; j < SLOTS; j++) xr[j] = xv[t + 256 * j];

    float acc[NR];
#pragma unroll
    for (int r = 0; r < NR; r++) {
        const unsigned mb = (r & 1) ? mb1 : mb0;
        mbar_wait(mb, (r >> 1) & 1);

        const float4* sb = sbuf + (r & 1) * ROW_F4 + t;
        float a0 = 0.f, a1 = 0.f;
#pragma unroll
        for (int j = 0; j < SLOTS; j += 2) {
            float4 w0 = sb[256 * j],       x0 = xr[j];
            float4 w1 = sb[256 * (j + 1)], x1 = xr[j + 1];
            a0 += w0.x * x0.x + w0.y * x0.y + w0.z * x0.z + w0.w * x0.w;
            a1 += w1.x * x1.x + w1.y * x1.y + w1.z * x1.z + w1.w * x1.w;
        }
        acc[r] = a0 + a1;

        __syncthreads();   // whole CTA done reading stage (r&1)
        if (r + 2 < NR && t == 0) {
            mbar_expect_tx(mb, ROW_BYTES);
            tma_bulk_g2s(smem_u32(sbuf + (r & 1) * ROW_F4),
                         W + (size_t)(rowbase + r + 2) * D, ROW_BYTES, mb);
        }
    }

#pragma unroll
    for (int r = 0; r < NR; r++) {
#pragma unroll
        for (int o = 16; o > 0; o >>= 1)
            acc[r] += __shfl_xor_sync(0xFFFFFFFFu, acc[r], o);
    }

    int warp = t >> 5;
    int lane = t & 31;
    if (lane == 0) {
#pragma unroll
        for (int r = 0; r < NR; r++) sred[warp][r] = acc[r];
    }
    if (t == 0) s_scale = rms_scale();
    __syncthreads();
    if (t < NR) {
        float s = 0.f;
#pragma unroll
        for (int w = 0; w < GTHREADS / 32; w++) s += sred[w][t];
        int row = rowbase + t;
        if (mode == 0) dst[row] = s_scale * s;
        else           dst[row] = s_scale * g_x[row] + s;
    }
}

// K1: fused Wr/Wk/Wv GEMV (scale folded into epilogue). ROWS=8, grid = 3072
#define ROWS3 8
__global__ void __launch_bounds__(GTHREADS, 3)
gemv3_kernel(const float* __restrict__ Wr,
             const float* __restrict__ Wk,
             const float* __restrict__ Wv) {
    const int blocks_per_mat = D / ROWS3;  // 1024
    int mat = blockIdx.x / blocks_per_mat;
    int rowbase = (blockIdx.x % blocks_per_mat) * ROWS3;
    const float* W = (mat == 0) ? Wr : ((mat == 1) ? Wk : Wv);
    float* dst = (mat == 0) ? g_rpre : ((mat == 1) ? g_k : g_v);
    gemv_pipe_tma<ROWS3>(W, g_x, rowbase, dst, 0);
}

// K3: h = scale*xg + Wo @ y. ROWS=4 (halves wave-quantization tail), grid = 2048
#define ROWSO 4
__global__ void __launch_bounds__(GTHREADS, 3)
gemv_o_kernel(const float* __restrict__ Wo) {
    int rowbase = blockIdx.x * ROWSO;
    gemv_pipe_tma<ROWSO>(Wo, g_y, rowbase, g_h, 1);
}

// ---------------------------------------------------------------------------
// K2: elementwise (decay, RoPE, Kalman gate) -> y   (proven)
// ---------------------------------------------------------------------------
__global__ void elemwise_kernel(const float* __restrict__ step_pos,
                                const float* __restrict__ state_num,
                                const float* __restrict__ state_den,
                                const float* __restrict__ state_var,
                                const float* __restrict__ raw_decay,
                                const float* __restrict__ pn_param,
                                const float* __restrict__ on_param,
                                const float* __restrict__ W_time) {
    int i = blockIdx.x * 256 + threadIdx.x;
    if (i >= D) return;

    float k = g_k[i];
    float v = g_v[i];
    if (i < 2 * M_TIME) {
        int m = i >> 1;
        float th = step_pos[0] * W_time[m];
        float c, s;
        sincosf(th, &s, &c);
        float v0 = g_v[2 * m];
        float v1 = g_v[2 * m + 1];
        v = (i & 1) ? (v0 * s + v1 * c) : (v0 * c - v1 * s);
    }

    float sp = softplusf(raw_decay[i]);
    float rate = fmaxf(-sp, -30.f);
    float lam = fmaxf(expf(rate), 1e-6f);
    float pn = fminf(fmaxf(softplusf(pn_param[0]), 1e-6f), 1e4f);
    float on = fminf(fmaxf(softplusf(on_param[0]), 1e-6f), 1e4f);

    float sn = state_num[i] * lam;
    float sd = state_den[i] * lam;
    float sv = state_var[i] * lam * lam + pn;

    float r = 1.f / (1.f + expf(-g_rpre[i]));
    float w = expf(fminf(k, 30.f));
    float pred_state = sn / (sd + 1e-6f);
    float msg = w * v;
    float resid = msg - pred_state;
    float obs_var = expf(fminf(-k, 30.f)) * on + 1e-6f;
    float gain = sv / (sv + obs_var);
    gain = fminf(fmaxf(gain, 1e-6f), 1.f - 1e-6f);
    float new_state = pred_state + gain * resid;
    g_y[i] = r * new_state;
}

// ---------------------------------------------------------------------------
// K4: exact KWTA_K-th-largest (radix select) + threshold. (proven gmem ver.)
// ---------------------------------------------------------------------------
__global__ void topk_kernel(float* __restrict__ out) {
    __shared__ unsigned hist[256];
    __shared__ unsigned s_prefix;
    __shared__ int s_K;
    __shared__ float s_thresh;

    if (threadIdx.x == 0) { s_prefix = 0u; s_K = KWTA_K; }
    __syncthreads();

    for (int pass = 3; pass >= 0; pass--) {
        if (threadIdx.x < 256) hist[threadIdx.x] = 0u;
        __syncthreads();
        unsigned prefmask = (pass == 3) ? 0u : (0xFFFFFFFFu << ((pass + 1) * 8));
        unsigned pref = s_prefix;
        for (int i = threadIdx.x; i < D; i += 1024) {
            unsigned u = __float_as_uint(g_h[i]);
            unsigned key = (u & 0x80000000u) ? ~u : (u | 0x80000000u);
            if ((key & prefmask) == (pref & prefmask)) {
                atomicAdd(&hist[(key >> (pass * 8)) & 255u], 1u);
            }
        }
        __syncthreads();
        if (threadIdx.x == 0) {
            int K = s_K;
            unsigned cum = 0;
            int b = 255;
            for (; b >= 0; b--) {
                cum += hist[b];
                if ((int)cum >= K) break;
            }
            s_K = K - (int)(cum - hist[b]);
            s_prefix = s_prefix | ((unsigned)b << (pass * 8));
        }
        __syncthreads();
    }

    if (threadIdx.x == 0) {
        unsigned key = s_prefix;
        unsigned u = (key & 0x80000000u) ? (key ^ 0x80000000u) : ~key;
        s_thresh = __uint_as_float(u);
    }
    __syncthreads();

    float th = s_thresh;
    for (int i = threadIdx.x; i < D; i += 1024) {
        float h = g_h[i];
        out[i] = (h >= th) ? h : 0.f;
    }
}

// ---------------------------------------------------------------------------
// Launch
// ---------------------------------------------------------------------------
extern "C" void kernel_launch(void* const* d_in, const int* in_sizes, int n_in,
                              void* d_out, int out_size) {
    const float* x_in      = (const float*)d_in[0];
    const float* step_pos  = (const float*)d_in[1];
    const float* pred      = (const float*)d_in[2];
    const float* state_num = (const float*)d_in[3];
    const float* state_den = (const float*)d_in[4];
    const float* state_var = (const float*)d_in[5];
    const float* Wr        = (const float*)d_in[6];
    const float* Wk        = (const float*)d_in[7];
    const float* Wv        = (const float*)d_in[8];
    const float* Wo        = (const float*)d_in[9];
    const float* raw_decay = (const float*)d_in[10];
    const float* pn_param  = (const float*)d_in[11];
    const float* on_param  = (const float*)d_in[12];
    const float* g_norm    = (const float*)d_in[13];
    const float* W_time    = (const float*)d_in[14];
    float* out = (float*)d_out;

    cudaFuncSetAttribute(gemv3_kernel,
                         cudaFuncAttributeMaxDynamicSharedMemorySize, SMEM_BYTES);
    cudaFuncSetAttribute(gemv_o_kernel,
                         cudaFuncAttributeMaxDynamicSharedMemorySize, SMEM_BYTES);

    prep_kernel<<<NPART, 256>>>(x_in, pred, g_norm);
    gemv3_kernel<<<3 * (D / ROWS3), GTHREADS, SMEM_BYTES>>>(Wr, Wk, Wv);
    elemwise_kernel<<<D / 256, 256>>>(step_pos, state_num, state_den, state_var,
                                      raw_decay, pn_param, on_param, W_time);
    gemv_o_kernel<<<D / ROWSO, GTHREADS, SMEM_BYTES>>>(Wo);
    topk_kernel<<<1, 1024>>>(out);
}